// round 5
// baseline (speedup 1.0000x reference)
#include <cuda_runtime.h>
#include <cstdint>

// EngramGating: B=16, S=16384, DIM=32, H=4  (T = 262144 tokens)
// out[t,h,k] = sigmoid(signed_sqrt(gate_raw[t,h])) * (emb[t] @ Wv^T + bv)[k]
// gate_raw[t,h] = sum_k( rms(key)*g1 * rms(q)*g2 ) / sqrt(32)
// key[t,h,k] = sum_d emb[t,d] * Wk[h,k,d] + bk[h,k]
//
// Mapping: lane l -> head h = l>>3, k in {4i..4i+3}, i = l&7.
//   - q load / out store: one float4 per lane (coalesced 512B per token)
//   - reductions: 3-step shfl butterfly within 8-lane groups (serves 4 heads/instr)
//   - value: lane=k mapping, redistributed via 4 shfl.idx
//   - weights in smem as d-pair f32x2 (u64); Wk swizzled for conflict-free LDS.64

#define DIM 32
#define HC  4
#define TTOK 8
#define WARPS_PER_BLOCK 4
#define THREADS (WARPS_PER_BLOCK * 32)
#define GRID_BLOCKS 444            // 148 SMs * 3 blocks (occupancy target 3)

#define WK_H_STRIDE 513            // odd u64 stride per head -> h shifts bank pairs

__device__ __forceinline__ void fma2(unsigned long long& acc,
                                     unsigned long long a,
                                     unsigned long long b) {
    asm("fma.rn.f32x2 %0, %1, %2, %0;" : "+l"(acc) : "l"(a), "l"(b));
}

__device__ __forceinline__ float hadd2(unsigned long long v) {
    return __uint_as_float((unsigned)v) + __uint_as_float((unsigned)(v >> 32));
}

__global__ void __launch_bounds__(THREADS, 3)
engram_gating_kernel(const float* __restrict__ emb,      // [T,32]
                     const float* __restrict__ hid,      // [T,4,32]
                     const float* __restrict__ Wv,       // [32,32]
                     const float* __restrict__ bv,       // [32]
                     const float* __restrict__ Wk,       // [4,32,32]
                     const float* __restrict__ bk,       // [4,32]
                     const float* __restrict__ g1,       // [4,32]
                     const float* __restrict__ g2,       // [4,32]
                     float* __restrict__ out,            // [T,4,32]
                     int nTok) {
    __shared__ unsigned long long sWk[HC * WK_H_STRIDE];   // swizzled [h][dp][k']
    __shared__ unsigned long long sWv[16 * 32];            // [dp][k]
    __shared__ __align__(16) float sE[WARPS_PER_BLOCK][TTOK * DIM];

    const int tid = threadIdx.x;

    // ---- stage weights ----
    {
        // Wk element (h,k,d): u64 index g covers d-pair dp of row (h,k)
        const unsigned long long* WkU = (const unsigned long long*)Wk;
        for (int gI = tid; gI < HC * 32 * 16; gI += THREADS) {
            int h = gI >> 9, k = (gI >> 4) & 31, dp = gI & 15;
            int ksw = k ^ (2 * ((k >> 4) & 1));   // bit1 ^= bit4 (i>=4 swizzle)
            sWk[h * WK_H_STRIDE + dp * 32 + ksw] = WkU[gI];
        }
        const unsigned long long* WvU = (const unsigned long long*)Wv;
        for (int gI = tid; gI < 32 * 16; gI += THREADS) {
            int k = gI >> 4, dp = gI & 15;
            sWv[dp * 32 + k] = WvU[gI];
        }
    }
    __syncthreads();

    const int lane = tid & 31;
    const int w = tid >> 5;
    const int hH = lane >> 3;          // head of this lane
    const int iI = lane & 7;           // index within 8-lane group
    const int sSw = 2 * (iI >> 2);     // swizzle term for this lane's k block

    // ---- per-lane constants in registers ----
    float bkc[4], ggc[4];
#pragma unroll
    for (int c = 0; c < 4; c++) {
        int k = 4 * iI + c;
        bkc[c] = bk[hH * DIM + k];
        ggc[c] = g1[hH * DIM + k] * g2[hH * DIM + k];
    }
    const float bvl = bv[lane];
    int wkoff[4];
#pragma unroll
    for (int c = 0; c < 4; c++)
        wkoff[c] = hH * WK_H_STRIDE + 4 * iI + (c ^ sSw);

    const int warpG = blockIdx.x * WARPS_PER_BLOCK + w;
    const int nWarps = gridDim.x * WARPS_PER_BLOCK;
    const int nGroups = (nTok + TTOK - 1) / TTOK;

    const float EPS = 1.1920929e-07f;
    const float INV32 = 0.03125f;
    const float INVSQRT32 = 0.17677669529663687f;

    for (int g = warpG; g < nGroups; g += nWarps) {
        const int tb = g * TTOK;
        const bool full = (tb + TTOK) <= nTok;

        // ---- stage emb for 8 tokens: 2 x LDG.128 per lane -> smem ----
        if (full) {
            const float4* ep = (const float4*)(emb + (size_t)tb * DIM);
            float4* sp = (float4*)sE[w];
            sp[lane] = ep[lane];
            sp[32 + lane] = ep[32 + lane];
        } else {
            for (int r = 0; r < 2; r++) {
                int fi = (r * 32 + lane) * 4;     // float index within group
                float4 v = make_float4(0.f, 0.f, 0.f, 0.f);
                int base = tb * DIM + fi;
                int lim = nTok * DIM;
                if (base + 3 < lim) v = *(const float4*)(emb + base);
                *(float4*)&sE[w][fi] = v;
            }
        }

        // ---- prefetch q: one float4 per lane per token ----
        float4 qv[TTOK];
#pragma unroll
        for (int t = 0; t < TTOK; t++) {
            int tok = tb + t;
            if (full || tok < nTok)
                qv[t] = *(const float4*)(hid + (size_t)tok * (HC * DIM) + lane * 4);
            else
                qv[t] = make_float4(0.f, 0.f, 0.f, 0.f);
        }

        __syncwarp();

        // ---- mat-vec: 4 keys (this lane's k's) + value (k=lane), 8 tokens ----
        unsigned long long acck[TTOK][4];
        unsigned long long accv[TTOK];
#pragma unroll
        for (int t = 0; t < TTOK; t++) {
            accv[t] = 0ull;
#pragma unroll
            for (int c = 0; c < 4; c++) acck[t][c] = 0ull;
        }

        const unsigned long long* eP = (const unsigned long long*)sE[w];
#pragma unroll
        for (int dp = 0; dp < 16; dp++) {
            unsigned long long wv  = sWv[dp * 32 + lane];
            unsigned long long wk0 = sWk[wkoff[0] + dp * 32];
            unsigned long long wk1 = sWk[wkoff[1] + dp * 32];
            unsigned long long wk2 = sWk[wkoff[2] + dp * 32];
            unsigned long long wk3 = sWk[wkoff[3] + dp * 32];
#pragma unroll
            for (int t = 0; t < TTOK; t++) {
                unsigned long long e2 = eP[t * 16 + dp];   // broadcast LDS.64
                fma2(accv[t], wv, e2);
                fma2(acck[t][0], wk0, e2);
                fma2(acck[t][1], wk1, e2);
                fma2(acck[t][2], wk2, e2);
                fma2(acck[t][3], wk3, e2);
            }
        }
        __syncwarp();   // protect sE before next iteration overwrites

        // ---- epilogue per token ----
#pragma unroll
        for (int t = 0; t < TTOK; t++) {
            int tok = tb + t;
            if (full || tok < nTok) {
                float k0 = hadd2(acck[t][0]) + bkc[0];
                float k1 = hadd2(acck[t][1]) + bkc[1];
                float k2 = hadd2(acck[t][2]) + bkc[2];
                float k3 = hadd2(acck[t][3]) + bkc[3];
                float4 q = qv[t];

                float kk = k0 * k0 + k1 * k1 + k2 * k2 + k3 * k3;
                float qq = q.x * q.x + q.y * q.y + q.z * q.z + q.w * q.w;
                float kq = k0 * ggc[0] * q.x + k1 * ggc[1] * q.y
                         + k2 * ggc[2] * q.z + k3 * ggc[3] * q.w;

                // 3-step butterfly within 8-lane group (one instr serves 4 heads)
#pragma unroll
                for (int m = 1; m < 8; m <<= 1) {
                    kk += __shfl_xor_sync(0xffffffffu, kk, m);
                    qq += __shfl_xor_sync(0xffffffffu, qq, m);
                    kq += __shfl_xor_sync(0xffffffffu, kq, m);
                }

                float r = kq * rsqrtf(fmaf(kk, INV32, EPS))
                             * rsqrtf(fmaf(qq, INV32, EPS)) * INVSQRT32;
                float a = sqrtf(fmaxf(fabsf(r), 1e-6f));
                a = (r > 0.f) ? a : ((r < 0.f) ? -a : 0.f);
                float gate = 1.0f / (1.0f + __expf(-a));

                // value on lane=k mapping -> redistribute to this lane's 4 k's
                float val = hadd2(accv[t]) + bvl;
                float v0 = __shfl_sync(0xffffffffu, val, 4 * iI + 0);
                float v1 = __shfl_sync(0xffffffffu, val, 4 * iI + 1);
                float v2 = __shfl_sync(0xffffffffu, val, 4 * iI + 2);
                float v3 = __shfl_sync(0xffffffffu, val, 4 * iI + 3);

                float4 o = make_float4(gate * v0, gate * v1, gate * v2, gate * v3);
                *(float4*)(out + (size_t)tok * (HC * DIM) + lane * 4) = o;
            }
        }
    }
}

extern "C" void kernel_launch(void* const* d_in, const int* in_sizes, int n_in,
                              void* d_out, int out_size) {
    const float* emb = (const float*)d_in[0];
    const float* hid = (const float*)d_in[1];
    const float* Wv  = (const float*)d_in[2];
    const float* bv  = (const float*)d_in[3];
    const float* Wk  = (const float*)d_in[4];
    const float* bk  = (const float*)d_in[5];
    const float* g1  = (const float*)d_in[6];
    const float* g2  = (const float*)d_in[7];
    float* out = (float*)d_out;

    int nTok = in_sizes[0] / DIM;

    engram_gating_kernel<<<GRID_BLOCKS, THREADS>>>(
        emb, hid, Wv, bv, Wk, bk, g1, g2, out, nTok);
}